// round 15
// baseline (speedup 1.0000x reference)
#include <cuda_runtime.h>
#include <cuda_bf16.h>
#include <cstdint>

typedef unsigned long long u64;
typedef unsigned int u32;
typedef __nv_bfloat16 bf16;

constexpr int N_ELEC = 8192;
constexpr int DIM    = 256;
constexpr int NNB    = 24;
constexpr int F0     = 32;
constexpr int F1     = 16;
constexpr int NENV   = 8;
constexpr float CUTOFF = 5.0f;

// ---------------- scratch (device globals; no allocation) ----------------
__device__ float g_e1  [N_ELEC * DIM];
__device__ float g_hmsg[N_ELEC * DIM];
__device__ bf16 g_e1h[N_ELEC * DIM], g_e1l[N_ELEC * DIM];
__device__ bf16 g_t1h[N_ELEC * DIM], g_t1l[N_ELEC * DIM];
__device__ bf16 g_t2h[N_ELEC * DIM], g_t2l[N_ELEC * DIM];
__device__ bf16 g_w0h[DIM * DIM], g_w0l[DIM * DIM];
__device__ bf16 g_w1h[DIM * DIM], g_w1l[DIM * DIM];
__device__ bf16 g_w2h[DIM * DIM], g_w2l[DIM * DIM];
__device__ bf16 g_w3h[DIM * DIM], g_w3l[DIM * DIM];

// ---------------- helpers ----------------
__device__ __forceinline__ u64 pk2(float x, float y) {
    u64 r; asm("mov.b64 %0, {%1,%2};" : "=l"(r) : "f"(x), "f"(y)); return r;
}
__device__ __forceinline__ float2 upk2(u64 v) {
    float2 f; asm("mov.b64 {%0,%1}, %2;" : "=f"(f.x), "=f"(f.y) : "l"(v)); return f;
}
__device__ __forceinline__ u64 f2fma(u64 a, u64 b, u64 c) {
    u64 d; asm("fma.rn.f32x2 %0, %1, %2, %3;" : "=l"(d) : "l"(a), "l"(b), "l"(c));
    return d;
}
__device__ __forceinline__ u64 f2add(u64 a, u64 b) {
    u64 d; asm("add.rn.f32x2 %0, %1, %2;" : "=l"(d) : "l"(a), "l"(b));
    return d;
}
__device__ __forceinline__ float silu_f(float x) {
    float e = __expf(-x);
    return __fdividef(x, 1.0f + e);
}

__device__ __forceinline__ void mma_bf16(
    float c[4], u32 a0, u32 a1, u32 a2, u32 a3, u32 b0, u32 b1)
{
    asm volatile(
        "mma.sync.aligned.m16n8k16.row.col.f32.bf16.bf16.f32 "
        "{%0,%1,%2,%3}, {%4,%5,%6,%7}, {%8,%9}, {%0,%1,%2,%3};"
        : "+f"(c[0]), "+f"(c[1]), "+f"(c[2]), "+f"(c[3])
        : "r"(a0), "r"(a1), "r"(a2), "r"(a3), "r"(b0), "r"(b1));
}

__device__ __forceinline__ void ldm_x4(u32 r[4], u32 addr) {
    asm volatile(
        "ldmatrix.sync.aligned.m8n8.x4.shared.b16 {%0,%1,%2,%3}, [%4];"
        : "=r"(r[0]), "=r"(r[1]), "=r"(r[2]), "=r"(r[3]) : "r"(addr));
}

__device__ __forceinline__ void cp16(u32 dst, const void* src) {
    asm volatile("cp.async.cg.shared.global [%0], [%1], 16;"
                 :: "r"(dst), "l"(src));
}
#define CP_COMMIT() asm volatile("cp.async.commit_group;" ::: "memory")
#define CP_WAIT(n)  asm volatile("cp.async.wait_group %0;" :: "n"(n) : "memory")

// ---------------- prep: merged transpose-split of 4 weight matrices ----------
__global__ __launch_bounds__(256) void split_weights(
    const float* __restrict__ W0, const float* __restrict__ W1,
    const float* __restrict__ W2, const float* __restrict__ W3,
    bf16* __restrict__ o0h, bf16* __restrict__ o0l,
    bf16* __restrict__ o1h, bf16* __restrict__ o1l,
    bf16* __restrict__ o2h, bf16* __restrict__ o2l,
    bf16* __restrict__ o3h, bf16* __restrict__ o3l)
{
    __shared__ float t[32][33];
    const int z = blockIdx.z;
    const float* W = (z == 0) ? W0 : (z == 1) ? W1 : (z == 2) ? W2 : W3;
    bf16* oh = (z == 0) ? o0h : (z == 1) ? o1h : (z == 2) ? o2h : o3h;
    bf16* ol = (z == 0) ? o0l : (z == 1) ? o1l : (z == 2) ? o2l : o3l;

    const int tx = threadIdx.x;
    const int ty = threadIdx.y;
    const int jb = blockIdx.x * 32;
    const int kb = blockIdx.y * 32;

#pragma unroll
    for (int i = 0; i < 4; i++)
        t[ty + i * 8][tx] = W[(size_t)(kb + ty + i * 8) * DIM + jb + tx];
    __syncthreads();

#pragma unroll
    for (int i = 0; i < 4; i++) {
        const float v = t[tx][ty + i * 8];
        const bf16 h = __float2bfloat16(v);
        const bf16 l = __float2bfloat16(v - __bfloat162float(h));
        const size_t o = (size_t)(jb + ty + i * 8) * DIM + kb + tx;
        oh[o] = h;
        ol[o] = l;
    }
}

// ---------------------------------------------------------------------------
// R9 GEMM (verbatim)
// ---------------------------------------------------------------------------
constexpr int LDT = 72;
constexpr int ARR = 64 * LDT;
constexpr int BUF = 4 * ARR;
constexpr int GSMEM = 2 * BUF * 2;    // 73728 bytes

template <int MODE>
__global__ __launch_bounds__(256) void gemm_mma(
    const float* __restrict__ A32,
    const bf16* __restrict__ Ah, const bf16* __restrict__ Al,
    const bf16* __restrict__ BTh, const bf16* __restrict__ BTl,
    const float* __restrict__ bias, const float* __restrict__ extra,
    const float* __restrict__ res, const float* __restrict__ scale_p,
    float* __restrict__ out_f32,
    bf16* __restrict__ out_h, bf16* __restrict__ out_l)
{
    extern __shared__ bf16 sm[];
    const u32 smb = (u32)__cvta_generic_to_shared(sm);

    const int tid  = threadIdx.x;
    const int wid  = tid >> 5;
    const int lane = tid & 31;
    const int wm   = wid & 1;
    const int wn   = wid >> 1;
    const int m0   = blockIdx.y * 64;
    const int n0   = blockIdx.x * 64;

    const int lr = lane >> 2;
    const int lc = (lane & 3) * 2;

    const int s0r = tid >> 3, s0v = tid & 7;
    const int s1r = s0r + 32, s1v = s0v;

    float acc[2][2][4];
#pragma unroll
    for (int i = 0; i < 2; i++)
#pragma unroll
        for (int j = 0; j < 2; j++)
#pragma unroll
            for (int q = 0; q < 4; q++) acc[i][j][q] = 0.0f;

    const int a_row = wm * 32 + ((lane >> 3) & 1) * 8 + (lane & 7);
    const int a_kof = (lane >> 4) << 3;
    const int b_row = wn * 16 + ((lane >> 4) << 3) + (lane & 7);
    const int b_kof = ((lane >> 3) & 1) << 3;

    const u32 so0 = (u32)(s0r * LDT + s0v * 8) * 2;
    const u32 so1 = (u32)(s1r * LDT + s1v * 8) * 2;

    float4 pa32[4];
    uint4  pbh[2], pbl[2];

    auto issue_chunk_async = [&](int c, int buf) {
        const int k0 = c * 64;
        const u32 ah_b = smb + (buf * BUF) * 2;
        const u32 al_b = ah_b + ARR * 2;
        const u32 bh_b = ah_b + 2 * ARR * 2;
        const u32 bl_b = ah_b + 3 * ARR * 2;
        const size_t ga0 = (size_t)(m0 + s0r) * DIM + k0 + s0v * 8;
        const size_t ga1 = (size_t)(m0 + s1r) * DIM + k0 + s1v * 8;
        const size_t gb0 = (size_t)(n0 + s0r) * DIM + k0 + s0v * 8;
        const size_t gb1 = (size_t)(n0 + s1r) * DIM + k0 + s1v * 8;
        cp16(ah_b + so0, Ah + ga0);
        cp16(ah_b + so1, Ah + ga1);
        cp16(al_b + so0, Al + ga0);
        cp16(al_b + so1, Al + ga1);
        cp16(bh_b + so0, BTh + gb0);
        cp16(bh_b + so1, BTh + gb1);
        cp16(bl_b + so0, BTl + gb0);
        cp16(bl_b + so1, BTl + gb1);
        CP_COMMIT();
    };

    auto fetch_chunk_m0 = [&](int c) {
        const int k0 = c * 64;
        pa32[0] = *(const float4*)(A32 + (size_t)(m0 + s0r) * DIM + k0 + s0v * 8);
        pa32[1] = *(const float4*)(A32 + (size_t)(m0 + s0r) * DIM + k0 + s0v * 8 + 4);
        pa32[2] = *(const float4*)(A32 + (size_t)(m0 + s1r) * DIM + k0 + s1v * 8);
        pa32[3] = *(const float4*)(A32 + (size_t)(m0 + s1r) * DIM + k0 + s1v * 8 + 4);
        pbh[0] = *(const uint4*)(BTh + (size_t)(n0 + s0r) * DIM + k0 + s0v * 8);
        pbl[0] = *(const uint4*)(BTl + (size_t)(n0 + s0r) * DIM + k0 + s0v * 8);
        pbh[1] = *(const uint4*)(BTh + (size_t)(n0 + s1r) * DIM + k0 + s1v * 8);
        pbl[1] = *(const uint4*)(BTl + (size_t)(n0 + s1r) * DIM + k0 + s1v * 8);
    };

    auto store_chunk_m0 = [&](int buf) {
        bf16* AhS = sm + buf * BUF;
        bf16* AlS = AhS + ARR;
        bf16* BhS = AhS + 2 * ARR;
        bf16* BlS = AhS + 3 * ARR;
        bf16 h[8], l[8];
        float v[8] = { pa32[0].x, pa32[0].y, pa32[0].z, pa32[0].w,
                       pa32[1].x, pa32[1].y, pa32[1].z, pa32[1].w };
#pragma unroll
        for (int j = 0; j < 8; j++) {
            h[j] = __float2bfloat16(v[j]);
            l[j] = __float2bfloat16(v[j] - __bfloat162float(h[j]));
        }
        *(uint4*)&AhS[s0r * LDT + s0v * 8] = *(uint4*)h;
        *(uint4*)&AlS[s0r * LDT + s0v * 8] = *(uint4*)l;
        float v2[8] = { pa32[2].x, pa32[2].y, pa32[2].z, pa32[2].w,
                        pa32[3].x, pa32[3].y, pa32[3].z, pa32[3].w };
#pragma unroll
        for (int j = 0; j < 8; j++) {
            h[j] = __float2bfloat16(v2[j]);
            l[j] = __float2bfloat16(v2[j] - __bfloat162float(h[j]));
        }
        *(uint4*)&AhS[s1r * LDT + s1v * 8] = *(uint4*)h;
        *(uint4*)&AlS[s1r * LDT + s1v * 8] = *(uint4*)l;
        *(uint4*)&BhS[s0r * LDT + s0v * 8] = pbh[0];
        *(uint4*)&BlS[s0r * LDT + s0v * 8] = pbl[0];
        *(uint4*)&BhS[s1r * LDT + s1v * 8] = pbh[1];
        *(uint4*)&BlS[s1r * LDT + s1v * 8] = pbl[1];
    };

    auto compute_chunk = [&](int buf) {
        const u32 ah_b = smb + (buf * BUF) * 2;
        const u32 al_b = ah_b + ARR * 2;
        const u32 bh_b = ah_b + 2 * ARR * 2;
        const u32 bl_b = ah_b + 3 * ARR * 2;
#pragma unroll
        for (int ks = 0; ks < 4; ks++) {
            const int kb = ks * 16;
            u32 ah[2][4], al[2][4], bh[4], bl[4];
#pragma unroll
            for (int mt = 0; mt < 2; mt++) {
                const u32 aoff = (u32)((a_row + mt * 16) * LDT + kb + a_kof) * 2;
                ldm_x4(ah[mt], ah_b + aoff);
                ldm_x4(al[mt], al_b + aoff);
            }
            const u32 boff = (u32)(b_row * LDT + kb + b_kof) * 2;
            ldm_x4(bh, bh_b + boff);
            ldm_x4(bl, bl_b + boff);
#pragma unroll
            for (int mt = 0; mt < 2; mt++)
#pragma unroll
                for (int nt = 0; nt < 2; nt++) {
                    mma_bf16(acc[mt][nt], ah[mt][0], ah[mt][1], ah[mt][2], ah[mt][3],
                             bh[nt * 2], bh[nt * 2 + 1]);
                    mma_bf16(acc[mt][nt], ah[mt][0], ah[mt][1], ah[mt][2], ah[mt][3],
                             bl[nt * 2], bl[nt * 2 + 1]);
                    mma_bf16(acc[mt][nt], al[mt][0], al[mt][1], al[mt][2], al[mt][3],
                             bh[nt * 2], bh[nt * 2 + 1]);
                }
        }
    };

    if (MODE == 0) {
        fetch_chunk_m0(0);
        store_chunk_m0(0);
        __syncthreads();
        for (int c = 0; c < 4; c++) {
            const int buf = c & 1;
            if (c < 3) fetch_chunk_m0(c + 1);
            compute_chunk(buf);
            if (c < 3) store_chunk_m0(buf ^ 1);
            __syncthreads();
        }
    } else {
        issue_chunk_async(0, 0);
        for (int c = 0; c < 4; c++) {
            const int buf = c & 1;
            if (c < 3) {
                issue_chunk_async(c + 1, buf ^ 1);
                CP_WAIT(1);
            } else {
                CP_WAIT(0);
            }
            __syncthreads();
            compute_chunk(buf);
            __syncthreads();
        }
    }

    float sc = 1.0f;
    if (MODE == 2) sc = *scale_p;

#pragma unroll
    for (int mt = 0; mt < 2; mt++)
#pragma unroll
        for (int nt = 0; nt < 2; nt++) {
            const int col = n0 + wn * 16 + nt * 8 + lc;
            const float2 bv = *(const float2*)(bias + col);
#pragma unroll
            for (int half = 0; half < 2; half++) {
                const int row = m0 + wm * 32 + mt * 16 + lr + half * 8;
                const size_t off = (size_t)row * DIM + col;
                float w0 = acc[mt][nt][2 * half + 0] + bv.x;
                float w1 = acc[mt][nt][2 * half + 1] + bv.y;
                if (MODE == 1) {
                    float2 e = *(const float2*)(extra + off);
                    w0 += e.x; w1 += e.y;
                }
                float o0 = silu_f(w0), o1 = silu_f(w1);
                if (MODE == 2) {
                    float2 rv = *(const float2*)(res + off);
                    o0 = (o0 + rv.x) * sc;
                    o1 = (o1 + rv.y) * sc;
                }
                if (MODE != 1)
                    *(float2*)(out_f32 + off) = make_float2(o0, o1);
                if (MODE != 2) {
                    bf16 h0 = __float2bfloat16(o0);
                    bf16 h1 = __float2bfloat16(o1);
                    bf16 l0 = __float2bfloat16(o0 - __bfloat162float(h0));
                    bf16 l1 = __float2bfloat16(o1 - __bfloat162float(h1));
                    bf16 hp[2] = { h0, h1 }, lp[2] = { l0, l1 };
                    *(u32*)(out_h + off) = *(u32*)hp;
                    *(u32*)(out_l + off) = *(u32*)lp;
                }
            }
        }
}

// ---------------------------------------------------------------------------
// Pair kernel: phase 1 = R9 verbatim; phase 2 = single-dot pointer-select.
//  hmsg[n,d] = sum_k u_k * (beta_k . w_sel[:,d]),  w_sel = Wsame or Wdiff.
// ---------------------------------------------------------------------------
constexpr int NPB   = 4;
constexpr int PAIRS = NPB * NNB;   // 96

__global__ __launch_bounds__(256) void pair_kernel(
    const float* __restrict__ elec1,
    const float* __restrict__ r,
    const float* __restrict__ r_nb,
    const int*   __restrict__ s,
    const int*   __restrict__ s_nb,
    const float* __restrict__ hinit_nb,
    const float* __restrict__ ee_scales,
    const float* __restrict__ ee_kernel,
    const float* __restrict__ ee_bias,
    const float* __restrict__ Wf,
    const float* __restrict__ bf,
    const float* __restrict__ Wsame,
    const float* __restrict__ Wdiff,
    float* __restrict__ hinit_msg)
{
    __shared__ __align__(16) float beta_s[PAIRS][F1];   // 6 KB
    __shared__ int  mask_s[PAIRS];
    __shared__ u64  ws2_s[8][DIM];                      // 16 KB (Wsame row-pairs)
    __shared__ u64  wd2_s[8][DIM];                      // 16 KB (Wdiff row-pairs)
    __shared__ float eek_s[4 * F0];
    __shared__ float eeb_s[F0];
    __shared__ float wf_s[(F0 + NENV) * F1];
    __shared__ float bfv_s[F1];
    __shared__ float scl_s[NENV];

    const int tid = threadIdx.x;
    const int n0  = blockIdx.x * NPB;

    for (int i = tid; i < 4 * F0; i += 256) eek_s[i] = ee_kernel[i];
    for (int i = tid; i < F0; i += 256)     eeb_s[i] = ee_bias[i];
    for (int i = tid; i < (F0 + NENV) * F1; i += 256) wf_s[i] = Wf[i];
    if (tid < F1)   bfv_s[tid] = bf[tid];
    if (tid < NENV) scl_s[tid] = ee_scales[tid];

#pragma unroll
    for (int i = 0; i < 8; i++) {
        ws2_s[i][tid] = pk2(Wsame[(2 * i) * DIM + tid], Wsame[(2 * i + 1) * DIM + tid]);
        wd2_s[i][tid] = pk2(Wdiff[(2 * i) * DIM + tid], Wdiff[(2 * i + 1) * DIM + tid]);
    }
    __syncthreads();

    // ---- Phase 1 (R9 verbatim) ----
    if (tid < PAIRS) {
        const int nl = tid / NNB;
        const int k  = tid % NNB;
        const int n  = n0 + nl;

        const float rx = r[n * 3 + 0];
        const float ry = r[n * 3 + 1];
        const float rz = r[n * 3 + 2];
        const float* rn = r_nb + (size_t)(n * NNB + k) * 3;
        const float dx = rn[0] - rx;
        const float dy = rn[1] - ry;
        const float dz = rn[2] - rz;
        const float dist = sqrtf(dx * dx + dy * dy + dz * dz + 1e-12f);

        float feats[4] = { dist, dx, dy, dz };
        float h[F0];
#pragma unroll
        for (int j = 0; j < F0; j++) {
            float t = eeb_s[j];
#pragma unroll
            for (int f = 0; f < 4; f++) t += feats[f] * eek_s[f * F0 + j];
            h[j] = silu_f(t);
        }
        float env[NENV];
#pragma unroll
        for (int e = 0; e < NENV; e++) {
            float q = __fdividef(dist, scl_s[e]);
            env[e] = __expf(-q * q);
        }
        const float xx  = dist * (1.0f / CUTOFF);
        const float cut = (dist < CUTOFF)
                        ? (1.0f - xx) * (1.0f - xx) * (1.0f + 2.0f * xx)
                        : 0.0f;
#pragma unroll
        for (int i = 0; i < F1; i++) {
            float b = bfv_s[i];
#pragma unroll
            for (int j = 0; j < F0; j++)   b += h[j]   * wf_s[j * F1 + i];
#pragma unroll
            for (int e = 0; e < NENV; e++) b += env[e] * wf_s[(F0 + e) * F1 + i];
            beta_s[tid][i] = b * cut;
        }
        mask_s[tid] = (s[n] == s_nb[n * NNB + k]) ? 1 : 0;
    }
    __syncthreads();

    // ---- Phase 2: single-dot with warp-uniform W column select ----
    const int d = tid;
    const u64* ws_col = &ws2_s[0][d];
    const u64* wd_col = &wd2_s[0][d];

#pragma unroll
    for (int nl = 0; nl < NPB; nl++) {
        const int n = n0 + nl;
        const float e1 = elec1[(size_t)n * DIM + d];
        const float* hb = hinit_nb + ((size_t)n * NNB) * DIM + d;

        u64 r2 = 0ull;
#pragma unroll
        for (int g = 0; g < 3; g++) {
            float uu[8];
#pragma unroll
            for (int kk = 0; kk < 8; kk++)
                uu[kk] = e1 + hb[(size_t)(g * 8 + kk) * DIM];
#pragma unroll
            for (int kk = 0; kk < 8; kk++)
                uu[kk] = silu_f(uu[kk]);
#pragma unroll
            for (int kk = 0; kk < 8; kk++) {
                const int pair = nl * NNB + g * 8 + kk;
                const u64* wp = mask_s[pair] ? ws_col : wd_col;
                const u64* bp = (const u64*)beta_s[pair];
                // two partial dp chains for ILP
                u64 dp0 = f2fma(bp[0], wp[0 * DIM], 0ull);
                u64 dp1 = f2fma(bp[1], wp[1 * DIM], 0ull);
                dp0 = f2fma(bp[2], wp[2 * DIM], dp0);
                dp1 = f2fma(bp[3], wp[3 * DIM], dp1);
                dp0 = f2fma(bp[4], wp[4 * DIM], dp0);
                dp1 = f2fma(bp[5], wp[5 * DIM], dp1);
                dp0 = f2fma(bp[6], wp[6 * DIM], dp0);
                dp1 = f2fma(bp[7], wp[7 * DIM], dp1);
                const u64 dp = f2add(dp0, dp1);
                r2 = f2fma(pk2(uu[kk], uu[kk]), dp, r2);
            }
        }
        float2 rr = upk2(r2);
        hinit_msg[(size_t)n * DIM + d] = rr.x + rr.y;
    }
}

// ---------------------------------------------------------------------------
extern "C" void kernel_launch(void* const* d_in, const int* in_sizes, int n_in,
                              void* d_out, int out_size)
{
    const float* elec     = (const float*)d_in[0];
    const float* msg      = (const float*)d_in[1];
    const float* r        = (const float*)d_in[2];
    const float* r_nb     = (const float*)d_in[3];
    const int*   s        = (const int*)  d_in[4];
    const int*   s_nb     = (const int*)  d_in[5];
    const float* hinit_nb = (const float*)d_in[6];
    const float* W_in     = (const float*)d_in[7];
    const float* b_in     = (const float*)d_in[8];
    const float* ee_scales= (const float*)d_in[9];
    const float* ee_kernel= (const float*)d_in[10];
    const float* ee_bias  = (const float*)d_in[11];
    const float* Wf       = (const float*)d_in[12];
    const float* bf       = (const float*)d_in[13];
    const float* Wsame    = (const float*)d_in[14];
    const float* Wdiff    = (const float*)d_in[15];
    const float* W1       = (const float*)d_in[16];
    const float* b1       = (const float*)d_in[17];
    const float* W2       = (const float*)d_in[18];
    const float* b2       = (const float*)d_in[19];
    const float* W3       = (const float*)d_in[20];
    const float* b3       = (const float*)d_in[21];
    const float* scale    = (const float*)d_in[22];

    float* out = (float*)d_out;

    float *e1, *hmsg;
    bf16 *e1h, *e1l, *t1h, *t1l, *t2h, *t2l;
    bf16 *w0h, *w0l, *w1h, *w1l, *w2h, *w2l, *w3h, *w3l;
    cudaGetSymbolAddress((void**)&e1,   g_e1);
    cudaGetSymbolAddress((void**)&hmsg, g_hmsg);
    cudaGetSymbolAddress((void**)&e1h, g_e1h); cudaGetSymbolAddress((void**)&e1l, g_e1l);
    cudaGetSymbolAddress((void**)&t1h, g_t1h); cudaGetSymbolAddress((void**)&t1l, g_t1l);
    cudaGetSymbolAddress((void**)&t2h, g_t2h); cudaGetSymbolAddress((void**)&t2l, g_t2l);
    cudaGetSymbolAddress((void**)&w0h, g_w0h); cudaGetSymbolAddress((void**)&w0l, g_w0l);
    cudaGetSymbolAddress((void**)&w1h, g_w1h); cudaGetSymbolAddress((void**)&w1l, g_w1l);
    cudaGetSymbolAddress((void**)&w2h, g_w2h); cudaGetSymbolAddress((void**)&w2l, g_w2l);
    cudaGetSymbolAddress((void**)&w3h, g_w3h); cudaGetSymbolAddress((void**)&w3l, g_w3l);

    cudaFuncSetAttribute(gemm_mma<0>, cudaFuncAttributeMaxDynamicSharedMemorySize, GSMEM);
    cudaFuncSetAttribute(gemm_mma<1>, cudaFuncAttributeMaxDynamicSharedMemorySize, GSMEM);
    cudaFuncSetAttribute(gemm_mma<2>, cudaFuncAttributeMaxDynamicSharedMemorySize, GSMEM);

    split_weights<<<dim3(8, 8, 4), dim3(32, 8)>>>(
        W_in, W1, W2, W3, w0h, w0l, w1h, w1l, w2h, w2l, w3h, w3l);

    dim3 ggrid(DIM / 64, N_ELEC / 64);   // (4, 128) = 512 CTAs

    gemm_mma<0><<<ggrid, 256, GSMEM>>>(elec, nullptr, nullptr, w0h, w0l, b_in,
                                       nullptr, nullptr, nullptr, e1, e1h, e1l);

    pair_kernel<<<N_ELEC / NPB, 256>>>(e1, r, r_nb, s, s_nb, hinit_nb,
                                       ee_scales, ee_kernel, ee_bias, Wf, bf,
                                       Wsame, Wdiff, hmsg);

    gemm_mma<1><<<ggrid, 256, GSMEM>>>(nullptr, e1h, e1l, w1h, w1l, b1,
                                       hmsg, nullptr, nullptr, nullptr, t1h, t1l);
    gemm_mma<1><<<ggrid, 256, GSMEM>>>(nullptr, t1h, t1l, w2h, w2l, b2,
                                       msg, nullptr, nullptr, nullptr, t2h, t2l);
    gemm_mma<2><<<ggrid, 256, GSMEM>>>(nullptr, t2h, t2l, w3h, w3l, b3,
                                       nullptr, e1, scale, out, nullptr, nullptr);
}

// round 16
// speedup vs baseline: 1.0729x; 1.0729x over previous
#include <cuda_runtime.h>
#include <cuda_bf16.h>
#include <cstdint>

typedef unsigned long long u64;
typedef unsigned int u32;
typedef __nv_bfloat16 bf16;

constexpr int N_ELEC = 8192;
constexpr int DIM    = 256;
constexpr int NNB    = 24;
constexpr int F0     = 32;
constexpr int F1     = 16;
constexpr int NENV   = 8;
constexpr float CUTOFF = 5.0f;

// ---------------- scratch (device globals; no allocation) ----------------
__device__ float g_e1  [N_ELEC * DIM];
__device__ float g_hmsg[N_ELEC * DIM];
__device__ bf16 g_e1h[N_ELEC * DIM], g_e1l[N_ELEC * DIM];
__device__ bf16 g_t1h[N_ELEC * DIM], g_t1l[N_ELEC * DIM];
__device__ bf16 g_t2h[N_ELEC * DIM], g_t2l[N_ELEC * DIM];
__device__ bf16 g_w0h[DIM * DIM], g_w0l[DIM * DIM];
__device__ bf16 g_w1h[DIM * DIM], g_w1l[DIM * DIM];
__device__ bf16 g_w2h[DIM * DIM], g_w2l[DIM * DIM];
__device__ bf16 g_w3h[DIM * DIM], g_w3l[DIM * DIM];

// ---------------- helpers ----------------
__device__ __forceinline__ u64 pk2(float x, float y) {
    u64 r; asm("mov.b64 %0, {%1,%2};" : "=l"(r) : "f"(x), "f"(y)); return r;
}
__device__ __forceinline__ float2 upk2(u64 v) {
    float2 f; asm("mov.b64 {%0,%1}, %2;" : "=f"(f.x), "=f"(f.y) : "l"(v)); return f;
}
__device__ __forceinline__ u64 f2fma(u64 a, u64 b, u64 c) {
    u64 d; asm("fma.rn.f32x2 %0, %1, %2, %3;" : "=l"(d) : "l"(a), "l"(b), "l"(c));
    return d;
}
__device__ __forceinline__ float silu_f(float x) {
    float e = __expf(-x);
    return __fdividef(x, 1.0f + e);
}

__device__ __forceinline__ void mma_bf16(
    float c[4], u32 a0, u32 a1, u32 a2, u32 a3, u32 b0, u32 b1)
{
    asm volatile(
        "mma.sync.aligned.m16n8k16.row.col.f32.bf16.bf16.f32 "
        "{%0,%1,%2,%3}, {%4,%5,%6,%7}, {%8,%9}, {%0,%1,%2,%3};"
        : "+f"(c[0]), "+f"(c[1]), "+f"(c[2]), "+f"(c[3])
        : "r"(a0), "r"(a1), "r"(a2), "r"(a3), "r"(b0), "r"(b1));
}

__device__ __forceinline__ void ldm_x4(u32 r[4], u32 addr) {
    asm volatile(
        "ldmatrix.sync.aligned.m8n8.x4.shared.b16 {%0,%1,%2,%3}, [%4];"
        : "=r"(r[0]), "=r"(r[1]), "=r"(r[2]), "=r"(r[3]) : "r"(addr));
}

__device__ __forceinline__ void cp16(u32 dst, const void* src) {
    asm volatile("cp.async.cg.shared.global [%0], [%1], 16;"
                 :: "r"(dst), "l"(src));
}
#define CP_COMMIT() asm volatile("cp.async.commit_group;" ::: "memory")
#define CP_WAIT(n)  asm volatile("cp.async.wait_group %0;" :: "n"(n) : "memory")

// ---------------- prep: merged transpose-split of 4 weight matrices ----------
__global__ __launch_bounds__(256) void split_weights(
    const float* __restrict__ W0, const float* __restrict__ W1,
    const float* __restrict__ W2, const float* __restrict__ W3,
    bf16* __restrict__ o0h, bf16* __restrict__ o0l,
    bf16* __restrict__ o1h, bf16* __restrict__ o1l,
    bf16* __restrict__ o2h, bf16* __restrict__ o2l,
    bf16* __restrict__ o3h, bf16* __restrict__ o3l)
{
    __shared__ float t[32][33];
    const int z = blockIdx.z;
    const float* W = (z == 0) ? W0 : (z == 1) ? W1 : (z == 2) ? W2 : W3;
    bf16* oh = (z == 0) ? o0h : (z == 1) ? o1h : (z == 2) ? o2h : o3h;
    bf16* ol = (z == 0) ? o0l : (z == 1) ? o1l : (z == 2) ? o2l : o3l;

    const int tx = threadIdx.x;
    const int ty = threadIdx.y;
    const int jb = blockIdx.x * 32;
    const int kb = blockIdx.y * 32;

#pragma unroll
    for (int i = 0; i < 4; i++)
        t[ty + i * 8][tx] = W[(size_t)(kb + ty + i * 8) * DIM + jb + tx];
    __syncthreads();

#pragma unroll
    for (int i = 0; i < 4; i++) {
        const float v = t[tx][ty + i * 8];
        const bf16 h = __float2bfloat16(v);
        const bf16 l = __float2bfloat16(v - __bfloat162float(h));
        const size_t o = (size_t)(jb + ty + i * 8) * DIM + kb + tx;
        oh[o] = h;
        ol[o] = l;
    }
}

// ---------------------------------------------------------------------------
// mma.sync GEMM: CTA 64x64, K chunks of 64 double-buffered, ldmatrix + HMMA.
// D = Ah@Bh + Ah@Bl + Al@Bh (fp32 regs).
// MODE 0: A f32 (split in staging, register path); f32 + hi/lo out
// MODE 1: hi/lo A via cp.async; hi/lo out (+extra)
// MODE 2: hi/lo A via cp.async; f32 out = (silu(acc+bias)+res)*scale
// ---------------------------------------------------------------------------
constexpr int LDT = 72;
constexpr int ARR = 64 * LDT;
constexpr int BUF = 4 * ARR;
constexpr int GSMEM = 2 * BUF * 2;    // 73728 bytes

template <int MODE>
__global__ __launch_bounds__(256) void gemm_mma(
    const float* __restrict__ A32,
    const bf16* __restrict__ Ah, const bf16* __restrict__ Al,
    const bf16* __restrict__ BTh, const bf16* __restrict__ BTl,
    const float* __restrict__ bias, const float* __restrict__ extra,
    const float* __restrict__ res, const float* __restrict__ scale_p,
    float* __restrict__ out_f32,
    bf16* __restrict__ out_h, bf16* __restrict__ out_l)
{
    extern __shared__ bf16 sm[];
    const u32 smb = (u32)__cvta_generic_to_shared(sm);

    const int tid  = threadIdx.x;
    const int wid  = tid >> 5;
    const int lane = tid & 31;
    const int wm   = wid & 1;
    const int wn   = wid >> 1;
    const int m0   = blockIdx.y * 64;
    const int n0   = blockIdx.x * 64;

    const int lr = lane >> 2;
    const int lc = (lane & 3) * 2;

    const int s0r = tid >> 3, s0v = tid & 7;
    const int s1r = s0r + 32, s1v = s0v;

    float acc[2][2][4];
#pragma unroll
    for (int i = 0; i < 2; i++)
#pragma unroll
        for (int j = 0; j < 2; j++)
#pragma unroll
            for (int q = 0; q < 4; q++) acc[i][j][q] = 0.0f;

    const int a_row = wm * 32 + ((lane >> 3) & 1) * 8 + (lane & 7);
    const int a_kof = (lane >> 4) << 3;
    const int b_row = wn * 16 + ((lane >> 4) << 3) + (lane & 7);
    const int b_kof = ((lane >> 3) & 1) << 3;

    const u32 so0 = (u32)(s0r * LDT + s0v * 8) * 2;
    const u32 so1 = (u32)(s1r * LDT + s1v * 8) * 2;

    float4 pa32[4];
    uint4  pbh[2], pbl[2];

    auto issue_chunk_async = [&](int c, int buf) {
        const int k0 = c * 64;
        const u32 ah_b = smb + (buf * BUF) * 2;
        const u32 al_b = ah_b + ARR * 2;
        const u32 bh_b = ah_b + 2 * ARR * 2;
        const u32 bl_b = ah_b + 3 * ARR * 2;
        const size_t ga0 = (size_t)(m0 + s0r) * DIM + k0 + s0v * 8;
        const size_t ga1 = (size_t)(m0 + s1r) * DIM + k0 + s1v * 8;
        const size_t gb0 = (size_t)(n0 + s0r) * DIM + k0 + s0v * 8;
        const size_t gb1 = (size_t)(n0 + s1r) * DIM + k0 + s1v * 8;
        cp16(ah_b + so0, Ah + ga0);
        cp16(ah_b + so1, Ah + ga1);
        cp16(al_b + so0, Al + ga0);
        cp16(al_b + so1, Al + ga1);
        cp16(bh_b + so0, BTh + gb0);
        cp16(bh_b + so1, BTh + gb1);
        cp16(bl_b + so0, BTl + gb0);
        cp16(bl_b + so1, BTl + gb1);
        CP_COMMIT();
    };

    auto fetch_chunk_m0 = [&](int c) {
        const int k0 = c * 64;
        pa32[0] = *(const float4*)(A32 + (size_t)(m0 + s0r) * DIM + k0 + s0v * 8);
        pa32[1] = *(const float4*)(A32 + (size_t)(m0 + s0r) * DIM + k0 + s0v * 8 + 4);
        pa32[2] = *(const float4*)(A32 + (size_t)(m0 + s1r) * DIM + k0 + s1v * 8);
        pa32[3] = *(const float4*)(A32 + (size_t)(m0 + s1r) * DIM + k0 + s1v * 8 + 4);
        pbh[0] = *(const uint4*)(BTh + (size_t)(n0 + s0r) * DIM + k0 + s0v * 8);
        pbl[0] = *(const uint4*)(BTl + (size_t)(n0 + s0r) * DIM + k0 + s0v * 8);
        pbh[1] = *(const uint4*)(BTh + (size_t)(n0 + s1r) * DIM + k0 + s1v * 8);
        pbl[1] = *(const uint4*)(BTl + (size_t)(n0 + s1r) * DIM + k0 + s1v * 8);
    };

    auto store_chunk_m0 = [&](int buf) {
        bf16* AhS = sm + buf * BUF;
        bf16* AlS = AhS + ARR;
        bf16* BhS = AhS + 2 * ARR;
        bf16* BlS = AhS + 3 * ARR;
        bf16 h[8], l[8];
        float v[8] = { pa32[0].x, pa32[0].y, pa32[0].z, pa32[0].w,
                       pa32[1].x, pa32[1].y, pa32[1].z, pa32[1].w };
#pragma unroll
        for (int j = 0; j < 8; j++) {
            h[j] = __float2bfloat16(v[j]);
            l[j] = __float2bfloat16(v[j] - __bfloat162float(h[j]));
        }
        *(uint4*)&AhS[s0r * LDT + s0v * 8] = *(uint4*)h;
        *(uint4*)&AlS[s0r * LDT + s0v * 8] = *(uint4*)l;
        float v2[8] = { pa32[2].x, pa32[2].y, pa32[2].z, pa32[2].w,
                        pa32[3].x, pa32[3].y, pa32[3].z, pa32[3].w };
#pragma unroll
        for (int j = 0; j < 8; j++) {
            h[j] = __float2bfloat16(v2[j]);
            l[j] = __float2bfloat16(v2[j] - __bfloat162float(h[j]));
        }
        *(uint4*)&AhS[s1r * LDT + s1v * 8] = *(uint4*)h;
        *(uint4*)&AlS[s1r * LDT + s1v * 8] = *(uint4*)l;
        *(uint4*)&BhS[s0r * LDT + s0v * 8] = pbh[0];
        *(uint4*)&BlS[s0r * LDT + s0v * 8] = pbl[0];
        *(uint4*)&BhS[s1r * LDT + s1v * 8] = pbh[1];
        *(uint4*)&BlS[s1r * LDT + s1v * 8] = pbl[1];
    };

    auto compute_chunk = [&](int buf) {
        const u32 ah_b = smb + (buf * BUF) * 2;
        const u32 al_b = ah_b + ARR * 2;
        const u32 bh_b = ah_b + 2 * ARR * 2;
        const u32 bl_b = ah_b + 3 * ARR * 2;
#pragma unroll
        for (int ks = 0; ks < 4; ks++) {
            const int kb = ks * 16;
            u32 ah[2][4], al[2][4], bh[4], bl[4];
#pragma unroll
            for (int mt = 0; mt < 2; mt++) {
                const u32 aoff = (u32)((a_row + mt * 16) * LDT + kb + a_kof) * 2;
                ldm_x4(ah[mt], ah_b + aoff);
                ldm_x4(al[mt], al_b + aoff);
            }
            const u32 boff = (u32)(b_row * LDT + kb + b_kof) * 2;
            ldm_x4(bh, bh_b + boff);
            ldm_x4(bl, bl_b + boff);
#pragma unroll
            for (int mt = 0; mt < 2; mt++)
#pragma unroll
                for (int nt = 0; nt < 2; nt++) {
                    mma_bf16(acc[mt][nt], ah[mt][0], ah[mt][1], ah[mt][2], ah[mt][3],
                             bh[nt * 2], bh[nt * 2 + 1]);
                    mma_bf16(acc[mt][nt], ah[mt][0], ah[mt][1], ah[mt][2], ah[mt][3],
                             bl[nt * 2], bl[nt * 2 + 1]);
                    mma_bf16(acc[mt][nt], al[mt][0], al[mt][1], al[mt][2], al[mt][3],
                             bh[nt * 2], bh[nt * 2 + 1]);
                }
        }
    };

    if (MODE == 0) {
        fetch_chunk_m0(0);
        store_chunk_m0(0);
        __syncthreads();
        for (int c = 0; c < 4; c++) {
            const int buf = c & 1;
            if (c < 3) fetch_chunk_m0(c + 1);
            compute_chunk(buf);
            if (c < 3) store_chunk_m0(buf ^ 1);
            __syncthreads();
        }
    } else {
        issue_chunk_async(0, 0);
        for (int c = 0; c < 4; c++) {
            const int buf = c & 1;
            if (c < 3) {
                issue_chunk_async(c + 1, buf ^ 1);
                CP_WAIT(1);
            } else {
                CP_WAIT(0);
            }
            __syncthreads();
            compute_chunk(buf);
            __syncthreads();
        }
    }

    // ---- epilogue ----
    float sc = 1.0f;
    if (MODE == 2) sc = *scale_p;

#pragma unroll
    for (int mt = 0; mt < 2; mt++)
#pragma unroll
        for (int nt = 0; nt < 2; nt++) {
            const int col = n0 + wn * 16 + nt * 8 + lc;
            const float2 bv = *(const float2*)(bias + col);
#pragma unroll
            for (int half = 0; half < 2; half++) {
                const int row = m0 + wm * 32 + mt * 16 + lr + half * 8;
                const size_t off = (size_t)row * DIM + col;
                float w0 = acc[mt][nt][2 * half + 0] + bv.x;
                float w1 = acc[mt][nt][2 * half + 1] + bv.y;
                if (MODE == 1) {
                    float2 e = *(const float2*)(extra + off);
                    w0 += e.x; w1 += e.y;
                }
                float o0 = silu_f(w0), o1 = silu_f(w1);
                if (MODE == 2) {
                    float2 rv = *(const float2*)(res + off);
                    o0 = (o0 + rv.x) * sc;
                    o1 = (o1 + rv.y) * sc;
                }
                if (MODE != 1)
                    *(float2*)(out_f32 + off) = make_float2(o0, o1);
                if (MODE != 2) {
                    bf16 h0 = __float2bfloat16(o0);
                    bf16 h1 = __float2bfloat16(o1);
                    bf16 l0 = __float2bfloat16(o0 - __bfloat162float(h0));
                    bf16 l1 = __float2bfloat16(o1 - __bfloat162float(h1));
                    bf16 hp[2] = { h0, h1 }, lp[2] = { l0, l1 };
                    *(u32*)(out_h + off) = *(u32*)hp;
                    *(u32*)(out_l + off) = *(u32*)lp;
                }
            }
        }
}

// ---------------------------------------------------------------------------
// Pair kernel: 4 electrons per block, 256 threads (NO occupancy forcing).
// Phase 1 stores beta + mask; phase 2 dual-accumulator (R9 structure, frozen).
// ---------------------------------------------------------------------------
constexpr int NPB   = 4;
constexpr int PAIRS = NPB * NNB;   // 96

__global__ __launch_bounds__(256) void pair_kernel(
    const float* __restrict__ elec1,
    const float* __restrict__ r,
    const float* __restrict__ r_nb,
    const int*   __restrict__ s,
    const int*   __restrict__ s_nb,
    const float* __restrict__ hinit_nb,
    const float* __restrict__ ee_scales,
    const float* __restrict__ ee_kernel,
    const float* __restrict__ ee_bias,
    const float* __restrict__ Wf,
    const float* __restrict__ bf,
    const float* __restrict__ Wsame,
    const float* __restrict__ Wdiff,
    float* __restrict__ hinit_msg)
{
    __shared__ __align__(16) float beta_s[PAIRS][F1];
    __shared__ float maskf_s[PAIRS];
    __shared__ u64  wd2_s [8][DIM];
    __shared__ u64  wsd2_s[8][DIM];
    __shared__ float eek_s[4 * F0];
    __shared__ float eeb_s[F0];
    __shared__ float wf_s[(F0 + NENV) * F1];
    __shared__ float bfv_s[F1];
    __shared__ float scl_s[NENV];

    const int tid = threadIdx.x;
    const int n0  = blockIdx.x * NPB;

    for (int i = tid; i < 4 * F0; i += 256) eek_s[i] = ee_kernel[i];
    for (int i = tid; i < F0; i += 256)     eeb_s[i] = ee_bias[i];
    for (int i = tid; i < (F0 + NENV) * F1; i += 256) wf_s[i] = Wf[i];
    if (tid < F1)   bfv_s[tid] = bf[tid];
    if (tid < NENV) scl_s[tid] = ee_scales[tid];

#pragma unroll
    for (int i = 0; i < 8; i++) {
        float d0 = Wdiff[(2 * i + 0) * DIM + tid];
        float d1 = Wdiff[(2 * i + 1) * DIM + tid];
        float s0 = Wsame[(2 * i + 0) * DIM + tid] - d0;
        float s1 = Wsame[(2 * i + 1) * DIM + tid] - d1;
        wd2_s [i][tid] = pk2(d0, d1);
        wsd2_s[i][tid] = pk2(s0, s1);
    }
    __syncthreads();

    if (tid < PAIRS) {
        const int nl = tid / NNB;
        const int k  = tid % NNB;
        const int n  = n0 + nl;

        const float rx = r[n * 3 + 0];
        const float ry = r[n * 3 + 1];
        const float rz = r[n * 3 + 2];
        const float* rn = r_nb + (size_t)(n * NNB + k) * 3;
        const float dx = rn[0] - rx;
        const float dy = rn[1] - ry;
        const float dz = rn[2] - rz;
        const float dist = sqrtf(dx * dx + dy * dy + dz * dz + 1e-12f);

        float feats[4] = { dist, dx, dy, dz };
        float h[F0];
#pragma unroll
        for (int j = 0; j < F0; j++) {
            float t = eeb_s[j];
#pragma unroll
            for (int f = 0; f < 4; f++) t += feats[f] * eek_s[f * F0 + j];
            h[j] = silu_f(t);
        }
        float env[NENV];
#pragma unroll
        for (int e = 0; e < NENV; e++) {
            float q = __fdividef(dist, scl_s[e]);
            env[e] = __expf(-q * q);
        }
        const float xx  = dist * (1.0f / CUTOFF);
        const float cut = (dist < CUTOFF)
                        ? (1.0f - xx) * (1.0f - xx) * (1.0f + 2.0f * xx)
                        : 0.0f;
#pragma unroll
        for (int i = 0; i < F1; i++) {
            float b = bfv_s[i];
#pragma unroll
            for (int j = 0; j < F0; j++)   b += h[j]   * wf_s[j * F1 + i];
#pragma unroll
            for (int e = 0; e < NENV; e++) b += env[e] * wf_s[(F0 + e) * F1 + i];
            beta_s[tid][i] = b * cut;
        }
        maskf_s[tid] = (s[n] == s_nb[n * NNB + k]) ? 1.0f : 0.0f;
    }
    __syncthreads();

    const int d = tid;
#pragma unroll
    for (int nl = 0; nl < NPB; nl++) {
        const int n = n0 + nl;
        const float e1 = elec1[(size_t)n * DIM + d];
        const float* hb = hinit_nb + ((size_t)n * NNB) * DIM + d;

        u64 vall[8], vsm[8];
#pragma unroll
        for (int i = 0; i < 8; i++) { vall[i] = 0ull; vsm[i] = 0ull; }

#pragma unroll
        for (int g = 0; g < 3; g++) {
            float uu[8];
#pragma unroll
            for (int kk = 0; kk < 8; kk++)
                uu[kk] = e1 + hb[(size_t)(g * 8 + kk) * DIM];
#pragma unroll
            for (int kk = 0; kk < 8; kk++)
                uu[kk] = silu_f(uu[kk]);
#pragma unroll
            for (int kk = 0; kk < 8; kk++) {
                const int pair = nl * NNB + g * 8 + kk;
                const float u  = uu[kk];
                const float um = u * maskf_s[pair];
                const u64 u2   = pk2(u, u);
                const u64 um2  = pk2(um, um);
                const u64* bp  = (const u64*)beta_s[pair];
#pragma unroll
                for (int i = 0; i < 8; i++) {
                    vall[i] = f2fma(u2,  bp[i], vall[i]);
                    vsm[i]  = f2fma(um2, bp[i], vsm[i]);
                }
            }
        }

        u64 r2 = 0ull;
#pragma unroll
        for (int i = 0; i < 8; i++) r2 = f2fma(wd2_s[i][d],  vall[i], r2);
#pragma unroll
        for (int i = 0; i < 8; i++) r2 = f2fma(wsd2_s[i][d], vsm[i],  r2);
        float2 rr = upk2(r2);
        hinit_msg[(size_t)n * DIM + d] = rr.x + rr.y;
    }
}

// ---------------------------------------------------------------------------
extern "C" void kernel_launch(void* const* d_in, const int* in_sizes, int n_in,
                              void* d_out, int out_size)
{
    const float* elec     = (const float*)d_in[0];
    const float* msg      = (const float*)d_in[1];
    const float* r        = (const float*)d_in[2];
    const float* r_nb     = (const float*)d_in[3];
    const int*   s        = (const int*)  d_in[4];
    const int*   s_nb     = (const int*)  d_in[5];
    const float* hinit_nb = (const float*)d_in[6];
    const float* W_in     = (const float*)d_in[7];
    const float* b_in     = (const float*)d_in[8];
    const float* ee_scales= (const float*)d_in[9];
    const float* ee_kernel= (const float*)d_in[10];
    const float* ee_bias  = (const float*)d_in[11];
    const float* Wf       = (const float*)d_in[12];
    const float* bf       = (const float*)d_in[13];
    const float* Wsame    = (const float*)d_in[14];
    const float* Wdiff    = (const float*)d_in[15];
    const float* W1       = (const float*)d_in[16];
    const float* b1       = (const float*)d_in[17];
    const float* W2       = (const float*)d_in[18];
    const float* b2       = (const float*)d_in[19];
    const float* W3       = (const float*)d_in[20];
    const float* b3       = (const float*)d_in[21];
    const float* scale    = (const float*)d_in[22];

    float* out = (float*)d_out;

    float *e1, *hmsg;
    bf16 *e1h, *e1l, *t1h, *t1l, *t2h, *t2l;
    bf16 *w0h, *w0l, *w1h, *w1l, *w2h, *w2l, *w3h, *w3l;
    cudaGetSymbolAddress((void**)&e1,   g_e1);
    cudaGetSymbolAddress((void**)&hmsg, g_hmsg);
    cudaGetSymbolAddress((void**)&e1h, g_e1h); cudaGetSymbolAddress((void**)&e1l, g_e1l);
    cudaGetSymbolAddress((void**)&t1h, g_t1h); cudaGetSymbolAddress((void**)&t1l, g_t1l);
    cudaGetSymbolAddress((void**)&t2h, g_t2h); cudaGetSymbolAddress((void**)&t2l, g_t2l);
    cudaGetSymbolAddress((void**)&w0h, g_w0h); cudaGetSymbolAddress((void**)&w0l, g_w0l);
    cudaGetSymbolAddress((void**)&w1h, g_w1h); cudaGetSymbolAddress((void**)&w1l, g_w1l);
    cudaGetSymbolAddress((void**)&w2h, g_w2h); cudaGetSymbolAddress((void**)&w2l, g_w2l);
    cudaGetSymbolAddress((void**)&w3h, g_w3h); cudaGetSymbolAddress((void**)&w3l, g_w3l);

    cudaFuncSetAttribute(gemm_mma<0>, cudaFuncAttributeMaxDynamicSharedMemorySize, GSMEM);
    cudaFuncSetAttribute(gemm_mma<1>, cudaFuncAttributeMaxDynamicSharedMemorySize, GSMEM);
    cudaFuncSetAttribute(gemm_mma<2>, cudaFuncAttributeMaxDynamicSharedMemorySize, GSMEM);

    split_weights<<<dim3(8, 8, 4), dim3(32, 8)>>>(
        W_in, W1, W2, W3, w0h, w0l, w1h, w1l, w2h, w2l, w3h, w3l);

    dim3 ggrid(DIM / 64, N_ELEC / 64);   // (4, 128) = 512 CTAs

    gemm_mma<0><<<ggrid, 256, GSMEM>>>(elec, nullptr, nullptr, w0h, w0l, b_in,
                                       nullptr, nullptr, nullptr, e1, e1h, e1l);

    pair_kernel<<<N_ELEC / NPB, 256>>>(e1, r, r_nb, s, s_nb, hinit_nb,
                                       ee_scales, ee_kernel, ee_bias, Wf, bf,
                                       Wsame, Wdiff, hmsg);

    gemm_mma<1><<<ggrid, 256, GSMEM>>>(nullptr, e1h, e1l, w1h, w1l, b1,
                                       hmsg, nullptr, nullptr, nullptr, t1h, t1l);
    gemm_mma<1><<<ggrid, 256, GSMEM>>>(nullptr, t1h, t1l, w2h, w2l, b2,
                                       msg, nullptr, nullptr, nullptr, t2h, t2l);
    gemm_mma<2><<<ggrid, 256, GSMEM>>>(nullptr, t2h, t2l, w3h, w3l, b3,
                                       nullptr, e1, scale, out, nullptr, nullptr);
}

// round 17
// speedup vs baseline: 1.0939x; 1.0195x over previous
#include <cuda_runtime.h>
#include <cuda_bf16.h>
#include <cstdint>

typedef unsigned long long u64;
typedef unsigned int u32;
typedef __nv_bfloat16 bf16;

constexpr int N_ELEC = 8192;
constexpr int DIM    = 256;
constexpr int NNB    = 24;
constexpr int F0     = 32;
constexpr int F1     = 16;
constexpr int NENV   = 8;
constexpr float CUTOFF = 5.0f;

// ---------------- scratch (device globals; no allocation) ----------------
__device__ float g_e1  [N_ELEC * DIM];
__device__ float g_hmsg[N_ELEC * DIM];
__device__ bf16 g_e1h[N_ELEC * DIM], g_e1l[N_ELEC * DIM];
__device__ bf16 g_t1h[N_ELEC * DIM], g_t1l[N_ELEC * DIM];
__device__ bf16 g_t2h[N_ELEC * DIM], g_t2l[N_ELEC * DIM];
__device__ bf16 g_w0h[DIM * DIM], g_w0l[DIM * DIM];
__device__ bf16 g_w1h[DIM * DIM], g_w1l[DIM * DIM];
__device__ bf16 g_w2h[DIM * DIM], g_w2l[DIM * DIM];
__device__ bf16 g_w3h[DIM * DIM], g_w3l[DIM * DIM];

// ---------------- helpers ----------------
__device__ __forceinline__ u64 pk2(float x, float y) {
    u64 r; asm("mov.b64 %0, {%1,%2};" : "=l"(r) : "f"(x), "f"(y)); return r;
}
__device__ __forceinline__ float2 upk2(u64 v) {
    float2 f; asm("mov.b64 {%0,%1}, %2;" : "=f"(f.x), "=f"(f.y) : "l"(v)); return f;
}
__device__ __forceinline__ u64 f2fma(u64 a, u64 b, u64 c) {
    u64 d; asm("fma.rn.f32x2 %0, %1, %2, %3;" : "=l"(d) : "l"(a), "l"(b), "l"(c));
    return d;
}
__device__ __forceinline__ float silu_f(float x) {
    float e = __expf(-x);
    return __fdividef(x, 1.0f + e);
}

__device__ __forceinline__ void mma_bf16(
    float c[4], u32 a0, u32 a1, u32 a2, u32 a3, u32 b0, u32 b1)
{
    asm volatile(
        "mma.sync.aligned.m16n8k16.row.col.f32.bf16.bf16.f32 "
        "{%0,%1,%2,%3}, {%4,%5,%6,%7}, {%8,%9}, {%0,%1,%2,%3};"
        : "+f"(c[0]), "+f"(c[1]), "+f"(c[2]), "+f"(c[3])
        : "r"(a0), "r"(a1), "r"(a2), "r"(a3), "r"(b0), "r"(b1));
}

__device__ __forceinline__ void ldm_x4(u32 r[4], u32 addr) {
    asm volatile(
        "ldmatrix.sync.aligned.m8n8.x4.shared.b16 {%0,%1,%2,%3}, [%4];"
        : "=r"(r[0]), "=r"(r[1]), "=r"(r[2]), "=r"(r[3]) : "r"(addr));
}

__device__ __forceinline__ void cp16(u32 dst, const void* src) {
    asm volatile("cp.async.cg.shared.global [%0], [%1], 16;"
                 :: "r"(dst), "l"(src));
}
#define CP_COMMIT() asm volatile("cp.async.commit_group;" ::: "memory")
#define CP_WAIT(n)  asm volatile("cp.async.wait_group %0;" :: "n"(n) : "memory")

// ---------------- prep: merged transpose-split of 4 weight matrices ----------
__global__ __launch_bounds__(256) void split_weights(
    const float* __restrict__ W0, const float* __restrict__ W1,
    const float* __restrict__ W2, const float* __restrict__ W3,
    bf16* __restrict__ o0h, bf16* __restrict__ o0l,
    bf16* __restrict__ o1h, bf16* __restrict__ o1l,
    bf16* __restrict__ o2h, bf16* __restrict__ o2l,
    bf16* __restrict__ o3h, bf16* __restrict__ o3l)
{
    __shared__ float t[32][33];
    const int z = blockIdx.z;
    const float* W = (z == 0) ? W0 : (z == 1) ? W1 : (z == 2) ? W2 : W3;
    bf16* oh = (z == 0) ? o0h : (z == 1) ? o1h : (z == 2) ? o2h : o3h;
    bf16* ol = (z == 0) ? o0l : (z == 1) ? o1l : (z == 2) ? o2l : o3l;

    const int tx = threadIdx.x;
    const int ty = threadIdx.y;
    const int jb = blockIdx.x * 32;
    const int kb = blockIdx.y * 32;

#pragma unroll
    for (int i = 0; i < 4; i++)
        t[ty + i * 8][tx] = W[(size_t)(kb + ty + i * 8) * DIM + jb + tx];
    __syncthreads();

#pragma unroll
    for (int i = 0; i < 4; i++) {
        const float v = t[tx][ty + i * 8];
        const bf16 h = __float2bfloat16(v);
        const bf16 l = __float2bfloat16(v - __bfloat162float(h));
        const size_t o = (size_t)(jb + ty + i * 8) * DIM + kb + tx;
        oh[o] = h;
        ol[o] = l;
    }
}

// ---------------------------------------------------------------------------
// mma.sync GEMM: CTA 64x64, K chunks of 64 double-buffered, ldmatrix + HMMA.
// D = Ah@Bh + Ah@Bl + Al@Bh (fp32 regs).
// MODE 0: A f32 (split in staging, register path); f32 + hi/lo out
// MODE 1: hi/lo A via cp.async; hi/lo out (+extra)
// MODE 2: hi/lo A via cp.async; f32 out = (silu(acc+bias)+res)*scale
// ---------------------------------------------------------------------------
constexpr int LDT = 72;
constexpr int ARR = 64 * LDT;
constexpr int BUF = 4 * ARR;
constexpr int GSMEM = 2 * BUF * 2;    // 73728 bytes

template <int MODE>
__global__ __launch_bounds__(256) void gemm_mma(
    const float* __restrict__ A32,
    const bf16* __restrict__ Ah, const bf16* __restrict__ Al,
    const bf16* __restrict__ BTh, const bf16* __restrict__ BTl,
    const float* __restrict__ bias, const float* __restrict__ extra,
    const float* __restrict__ res, const float* __restrict__ scale_p,
    float* __restrict__ out_f32,
    bf16* __restrict__ out_h, bf16* __restrict__ out_l)
{
    extern __shared__ bf16 sm[];
    const u32 smb = (u32)__cvta_generic_to_shared(sm);

    const int tid  = threadIdx.x;
    const int wid  = tid >> 5;
    const int lane = tid & 31;
    const int wm   = wid & 1;
    const int wn   = wid >> 1;
    const int m0   = blockIdx.y * 64;
    const int n0   = blockIdx.x * 64;

    const int lr = lane >> 2;
    const int lc = (lane & 3) * 2;

    const int s0r = tid >> 3, s0v = tid & 7;
    const int s1r = s0r + 32, s1v = s0v;

    float acc[2][2][4];
#pragma unroll
    for (int i = 0; i < 2; i++)
#pragma unroll
        for (int j = 0; j < 2; j++)
#pragma unroll
            for (int q = 0; q < 4; q++) acc[i][j][q] = 0.0f;

    const int a_row = wm * 32 + ((lane >> 3) & 1) * 8 + (lane & 7);
    const int a_kof = (lane >> 4) << 3;
    const int b_row = wn * 16 + ((lane >> 4) << 3) + (lane & 7);
    const int b_kof = ((lane >> 3) & 1) << 3;

    const u32 so0 = (u32)(s0r * LDT + s0v * 8) * 2;
    const u32 so1 = (u32)(s1r * LDT + s1v * 8) * 2;

    float4 pa32[4];
    uint4  pbh[2], pbl[2];

    auto issue_chunk_async = [&](int c, int buf) {
        const int k0 = c * 64;
        const u32 ah_b = smb + (buf * BUF) * 2;
        const u32 al_b = ah_b + ARR * 2;
        const u32 bh_b = ah_b + 2 * ARR * 2;
        const u32 bl_b = ah_b + 3 * ARR * 2;
        const size_t ga0 = (size_t)(m0 + s0r) * DIM + k0 + s0v * 8;
        const size_t ga1 = (size_t)(m0 + s1r) * DIM + k0 + s1v * 8;
        const size_t gb0 = (size_t)(n0 + s0r) * DIM + k0 + s0v * 8;
        const size_t gb1 = (size_t)(n0 + s1r) * DIM + k0 + s1v * 8;
        cp16(ah_b + so0, Ah + ga0);
        cp16(ah_b + so1, Ah + ga1);
        cp16(al_b + so0, Al + ga0);
        cp16(al_b + so1, Al + ga1);
        cp16(bh_b + so0, BTh + gb0);
        cp16(bh_b + so1, BTh + gb1);
        cp16(bl_b + so0, BTl + gb0);
        cp16(bl_b + so1, BTl + gb1);
        CP_COMMIT();
    };

    auto fetch_chunk_m0 = [&](int c) {
        const int k0 = c * 64;
        pa32[0] = *(const float4*)(A32 + (size_t)(m0 + s0r) * DIM + k0 + s0v * 8);
        pa32[1] = *(const float4*)(A32 + (size_t)(m0 + s0r) * DIM + k0 + s0v * 8 + 4);
        pa32[2] = *(const float4*)(A32 + (size_t)(m0 + s1r) * DIM + k0 + s1v * 8);
        pa32[3] = *(const float4*)(A32 + (size_t)(m0 + s1r) * DIM + k0 + s1v * 8 + 4);
        pbh[0] = *(const uint4*)(BTh + (size_t)(n0 + s0r) * DIM + k0 + s0v * 8);
        pbl[0] = *(const uint4*)(BTl + (size_t)(n0 + s0r) * DIM + k0 + s0v * 8);
        pbh[1] = *(const uint4*)(BTh + (size_t)(n0 + s1r) * DIM + k0 + s1v * 8);
        pbl[1] = *(const uint4*)(BTl + (size_t)(n0 + s1r) * DIM + k0 + s1v * 8);
    };

    auto store_chunk_m0 = [&](int buf) {
        bf16* AhS = sm + buf * BUF;
        bf16* AlS = AhS + ARR;
        bf16* BhS = AhS + 2 * ARR;
        bf16* BlS = AhS + 3 * ARR;
        bf16 h[8], l[8];
        float v[8] = { pa32[0].x, pa32[0].y, pa32[0].z, pa32[0].w,
                       pa32[1].x, pa32[1].y, pa32[1].z, pa32[1].w };
#pragma unroll
        for (int j = 0; j < 8; j++) {
            h[j] = __float2bfloat16(v[j]);
            l[j] = __float2bfloat16(v[j] - __bfloat162float(h[j]));
        }
        *(uint4*)&AhS[s0r * LDT + s0v * 8] = *(uint4*)h;
        *(uint4*)&AlS[s0r * LDT + s0v * 8] = *(uint4*)l;
        float v2[8] = { pa32[2].x, pa32[2].y, pa32[2].z, pa32[2].w,
                        pa32[3].x, pa32[3].y, pa32[3].z, pa32[3].w };
#pragma unroll
        for (int j = 0; j < 8; j++) {
            h[j] = __float2bfloat16(v2[j]);
            l[j] = __float2bfloat16(v2[j] - __bfloat162float(h[j]));
        }
        *(uint4*)&AhS[s1r * LDT + s1v * 8] = *(uint4*)h;
        *(uint4*)&AlS[s1r * LDT + s1v * 8] = *(uint4*)l;
        *(uint4*)&BhS[s0r * LDT + s0v * 8] = pbh[0];
        *(uint4*)&BlS[s0r * LDT + s0v * 8] = pbl[0];
        *(uint4*)&BhS[s1r * LDT + s1v * 8] = pbh[1];
        *(uint4*)&BlS[s1r * LDT + s1v * 8] = pbl[1];
    };

    auto compute_chunk = [&](int buf) {
        const u32 ah_b = smb + (buf * BUF) * 2;
        const u32 al_b = ah_b + ARR * 2;
        const u32 bh_b = ah_b + 2 * ARR * 2;
        const u32 bl_b = ah_b + 3 * ARR * 2;
#pragma unroll
        for (int ks = 0; ks < 4; ks++) {
            const int kb = ks * 16;
            u32 ah[2][4], al[2][4], bh[4], bl[4];
#pragma unroll
            for (int mt = 0; mt < 2; mt++) {
                const u32 aoff = (u32)((a_row + mt * 16) * LDT + kb + a_kof) * 2;
                ldm_x4(ah[mt], ah_b + aoff);
                ldm_x4(al[mt], al_b + aoff);
            }
            const u32 boff = (u32)(b_row * LDT + kb + b_kof) * 2;
            ldm_x4(bh, bh_b + boff);
            ldm_x4(bl, bl_b + boff);
#pragma unroll
            for (int mt = 0; mt < 2; mt++)
#pragma unroll
                for (int nt = 0; nt < 2; nt++) {
                    mma_bf16(acc[mt][nt], ah[mt][0], ah[mt][1], ah[mt][2], ah[mt][3],
                             bh[nt * 2], bh[nt * 2 + 1]);
                    mma_bf16(acc[mt][nt], ah[mt][0], ah[mt][1], ah[mt][2], ah[mt][3],
                             bl[nt * 2], bl[nt * 2 + 1]);
                    mma_bf16(acc[mt][nt], al[mt][0], al[mt][1], al[mt][2], al[mt][3],
                             bh[nt * 2], bh[nt * 2 + 1]);
                }
        }
    };

    if (MODE == 0) {
        fetch_chunk_m0(0);
        store_chunk_m0(0);
        __syncthreads();
        for (int c = 0; c < 4; c++) {
            const int buf = c & 1;
            if (c < 3) fetch_chunk_m0(c + 1);
            compute_chunk(buf);
            if (c < 3) store_chunk_m0(buf ^ 1);
            __syncthreads();
        }
    } else {
        issue_chunk_async(0, 0);
        for (int c = 0; c < 4; c++) {
            const int buf = c & 1;
            if (c < 3) {
                issue_chunk_async(c + 1, buf ^ 1);
                CP_WAIT(1);
            } else {
                CP_WAIT(0);
            }
            __syncthreads();
            compute_chunk(buf);
            __syncthreads();
        }
    }

    // ---- epilogue ----
    float sc = 1.0f;
    if (MODE == 2) sc = *scale_p;

#pragma unroll
    for (int mt = 0; mt < 2; mt++)
#pragma unroll
        for (int nt = 0; nt < 2; nt++) {
            const int col = n0 + wn * 16 + nt * 8 + lc;
            const float2 bv = *(const float2*)(bias + col);
#pragma unroll
            for (int half = 0; half < 2; half++) {
                const int row = m0 + wm * 32 + mt * 16 + lr + half * 8;
                const size_t off = (size_t)row * DIM + col;
                float w0 = acc[mt][nt][2 * half + 0] + bv.x;
                float w1 = acc[mt][nt][2 * half + 1] + bv.y;
                if (MODE == 1) {
                    float2 e = *(const float2*)(extra + off);
                    w0 += e.x; w1 += e.y;
                }
                float o0 = silu_f(w0), o1 = silu_f(w1);
                if (MODE == 2) {
                    float2 rv = *(const float2*)(res + off);
                    o0 = (o0 + rv.x) * sc;
                    o1 = (o1 + rv.y) * sc;
                }
                if (MODE != 1)
                    *(float2*)(out_f32 + off) = make_float2(o0, o1);
                if (MODE != 2) {
                    bf16 h0 = __float2bfloat16(o0);
                    bf16 h1 = __float2bfloat16(o1);
                    bf16 l0 = __float2bfloat16(o0 - __bfloat162float(h0));
                    bf16 l1 = __float2bfloat16(o1 - __bfloat162float(h1));
                    bf16 hp[2] = { h0, h1 }, lp[2] = { l0, l1 };
                    *(u32*)(out_h + off) = *(u32*)hp;
                    *(u32*)(out_l + off) = *(u32*)lp;
                }
            }
        }
}

// ---------------------------------------------------------------------------
// Pair kernel: 4 electrons per block, 256 threads.
// TRUE R9: outer nl loop NOT unrolled (critical for register allocation).
// ---------------------------------------------------------------------------
constexpr int NPB   = 4;
constexpr int PAIRS = NPB * NNB;   // 96

__global__ __launch_bounds__(256) void pair_kernel(
    const float* __restrict__ elec1,
    const float* __restrict__ r,
    const float* __restrict__ r_nb,
    const int*   __restrict__ s,
    const int*   __restrict__ s_nb,
    const float* __restrict__ hinit_nb,
    const float* __restrict__ ee_scales,
    const float* __restrict__ ee_kernel,
    const float* __restrict__ ee_bias,
    const float* __restrict__ Wf,
    const float* __restrict__ bf,
    const float* __restrict__ Wsame,
    const float* __restrict__ Wdiff,
    float* __restrict__ hinit_msg)
{
    __shared__ __align__(16) float beta_s[PAIRS][F1];
    __shared__ float maskf_s[PAIRS];
    __shared__ u64  wd2_s [8][DIM];
    __shared__ u64  wsd2_s[8][DIM];
    __shared__ float eek_s[4 * F0];
    __shared__ float eeb_s[F0];
    __shared__ float wf_s[(F0 + NENV) * F1];
    __shared__ float bfv_s[F1];
    __shared__ float scl_s[NENV];

    const int tid = threadIdx.x;
    const int n0  = blockIdx.x * NPB;

    for (int i = tid; i < 4 * F0; i += 256) eek_s[i] = ee_kernel[i];
    for (int i = tid; i < F0; i += 256)     eeb_s[i] = ee_bias[i];
    for (int i = tid; i < (F0 + NENV) * F1; i += 256) wf_s[i] = Wf[i];
    if (tid < F1)   bfv_s[tid] = bf[tid];
    if (tid < NENV) scl_s[tid] = ee_scales[tid];

#pragma unroll
    for (int i = 0; i < 8; i++) {
        float d0 = Wdiff[(2 * i + 0) * DIM + tid];
        float d1 = Wdiff[(2 * i + 1) * DIM + tid];
        float s0 = Wsame[(2 * i + 0) * DIM + tid] - d0;
        float s1 = Wsame[(2 * i + 1) * DIM + tid] - d1;
        wd2_s [i][tid] = pk2(d0, d1);
        wsd2_s[i][tid] = pk2(s0, s1);
    }
    __syncthreads();

    if (tid < PAIRS) {
        const int nl = tid / NNB;
        const int k  = tid % NNB;
        const int n  = n0 + nl;

        const float rx = r[n * 3 + 0];
        const float ry = r[n * 3 + 1];
        const float rz = r[n * 3 + 2];
        const float* rn = r_nb + (size_t)(n * NNB + k) * 3;
        const float dx = rn[0] - rx;
        const float dy = rn[1] - ry;
        const float dz = rn[2] - rz;
        const float dist = sqrtf(dx * dx + dy * dy + dz * dz + 1e-12f);

        float feats[4] = { dist, dx, dy, dz };
        float h[F0];
#pragma unroll
        for (int j = 0; j < F0; j++) {
            float t = eeb_s[j];
#pragma unroll
            for (int f = 0; f < 4; f++) t += feats[f] * eek_s[f * F0 + j];
            h[j] = silu_f(t);
        }
        float env[NENV];
#pragma unroll
        for (int e = 0; e < NENV; e++) {
            float q = __fdividef(dist, scl_s[e]);
            env[e] = __expf(-q * q);
        }
        const float xx  = dist * (1.0f / CUTOFF);
        const float cut = (dist < CUTOFF)
                        ? (1.0f - xx) * (1.0f - xx) * (1.0f + 2.0f * xx)
                        : 0.0f;
#pragma unroll
        for (int i = 0; i < F1; i++) {
            float b = bfv_s[i];
#pragma unroll
            for (int j = 0; j < F0; j++)   b += h[j]   * wf_s[j * F1 + i];
#pragma unroll
            for (int e = 0; e < NENV; e++) b += env[e] * wf_s[(F0 + e) * F1 + i];
            beta_s[tid][i] = b * cut;
        }
        maskf_s[tid] = (s[n] == s_nb[n * NNB + k]) ? 1.0f : 0.0f;
    }
    __syncthreads();

    const int d = tid;
    for (int nl = 0; nl < NPB; nl++) {
        const int n = n0 + nl;
        const float e1 = elec1[(size_t)n * DIM + d];
        const float* hb = hinit_nb + ((size_t)n * NNB) * DIM + d;

        u64 vall[8], vsm[8];
#pragma unroll
        for (int i = 0; i < 8; i++) { vall[i] = 0ull; vsm[i] = 0ull; }

#pragma unroll
        for (int g = 0; g < 3; g++) {
            float uu[8];
#pragma unroll
            for (int kk = 0; kk < 8; kk++)
                uu[kk] = e1 + hb[(size_t)(g * 8 + kk) * DIM];
#pragma unroll
            for (int kk = 0; kk < 8; kk++)
                uu[kk] = silu_f(uu[kk]);
#pragma unroll
            for (int kk = 0; kk < 8; kk++) {
                const int pair = nl * NNB + g * 8 + kk;
                const float u  = uu[kk];
                const float um = u * maskf_s[pair];
                const u64 u2   = pk2(u, u);
                const u64 um2  = pk2(um, um);
                const u64* bp  = (const u64*)beta_s[pair];
#pragma unroll
                for (int i = 0; i < 8; i++) {
                    vall[i] = f2fma(u2,  bp[i], vall[i]);
                    vsm[i]  = f2fma(um2, bp[i], vsm[i]);
                }
            }
        }

        u64 r2 = 0ull;
#pragma unroll
        for (int i = 0; i < 8; i++) r2 = f2fma(wd2_s[i][d],  vall[i], r2);
#pragma unroll
        for (int i = 0; i < 8; i++) r2 = f2fma(wsd2_s[i][d], vsm[i],  r2);
        float2 rr = upk2(r2);
        hinit_msg[(size_t)n * DIM + d] = rr.x + rr.y;
    }
}

// ---------------------------------------------------------------------------
extern "C" void kernel_launch(void* const* d_in, const int* in_sizes, int n_in,
                              void* d_out, int out_size)
{
    const float* elec     = (const float*)d_in[0];
    const float* msg      = (const float*)d_in[1];
    const float* r        = (const float*)d_in[2];
    const float* r_nb     = (const float*)d_in[3];
    const int*   s        = (const int*)  d_in[4];
    const int*   s_nb     = (const int*)  d_in[5];
    const float* hinit_nb = (const float*)d_in[6];
    const float* W_in     = (const float*)d_in[7];
    const float* b_in     = (const float*)d_in[8];
    const float* ee_scales= (const float*)d_in[9];
    const float* ee_kernel= (const float*)d_in[10];
    const float* ee_bias  = (const float*)d_in[11];
    const float* Wf       = (const float*)d_in[12];
    const float* bf       = (const float*)d_in[13];
    const float* Wsame    = (const float*)d_in[14];
    const float* Wdiff    = (const float*)d_in[15];
    const float* W1       = (const float*)d_in[16];
    const float* b1       = (const float*)d_in[17];
    const float* W2       = (const float*)d_in[18];
    const float* b2       = (const float*)d_in[19];
    const float* W3       = (const float*)d_in[20];
    const float* b3       = (const float*)d_in[21];
    const float* scale    = (const float*)d_in[22];

    float* out = (float*)d_out;

    float *e1, *hmsg;
    bf16 *e1h, *e1l, *t1h, *t1l, *t2h, *t2l;
    bf16 *w0h, *w0l, *w1h, *w1l, *w2h, *w2l, *w3h, *w3l;
    cudaGetSymbolAddress((void**)&e1,   g_e1);
    cudaGetSymbolAddress((void**)&hmsg, g_hmsg);
    cudaGetSymbolAddress((void**)&e1h, g_e1h); cudaGetSymbolAddress((void**)&e1l, g_e1l);
    cudaGetSymbolAddress((void**)&t1h, g_t1h); cudaGetSymbolAddress((void**)&t1l, g_t1l);
    cudaGetSymbolAddress((void**)&t2h, g_t2h); cudaGetSymbolAddress((void**)&t2l, g_t2l);
    cudaGetSymbolAddress((void**)&w0h, g_w0h); cudaGetSymbolAddress((void**)&w0l, g_w0l);
    cudaGetSymbolAddress((void**)&w1h, g_w1h); cudaGetSymbolAddress((void**)&w1l, g_w1l);
    cudaGetSymbolAddress((void**)&w2h, g_w2h); cudaGetSymbolAddress((void**)&w2l, g_w2l);
    cudaGetSymbolAddress((void**)&w3h, g_w3h); cudaGetSymbolAddress((void**)&w3l, g_w3l);

    cudaFuncSetAttribute(gemm_mma<0>, cudaFuncAttributeMaxDynamicSharedMemorySize, GSMEM);
    cudaFuncSetAttribute(gemm_mma<1>, cudaFuncAttributeMaxDynamicSharedMemorySize, GSMEM);
    cudaFuncSetAttribute(gemm_mma<2>, cudaFuncAttributeMaxDynamicSharedMemorySize, GSMEM);

    split_weights<<<dim3(8, 8, 4), dim3(32, 8)>>>(
        W_in, W1, W2, W3, w0h, w0l, w1h, w1l, w2h, w2l, w3h, w3l);

    dim3 ggrid(DIM / 64, N_ELEC / 64);   // (4, 128) = 512 CTAs

    gemm_mma<0><<<ggrid, 256, GSMEM>>>(elec, nullptr, nullptr, w0h, w0l, b_in,
                                       nullptr, nullptr, nullptr, e1, e1h, e1l);

    pair_kernel<<<N_ELEC / NPB, 256>>>(e1, r, r_nb, s, s_nb, hinit_nb,
                                       ee_scales, ee_kernel, ee_bias, Wf, bf,
                                       Wsame, Wdiff, hmsg);

    gemm_mma<1><<<ggrid, 256, GSMEM>>>(nullptr, e1h, e1l, w1h, w1l, b1,
                                       hmsg, nullptr, nullptr, nullptr, t1h, t1l);
    gemm_mma<1><<<ggrid, 256, GSMEM>>>(nullptr, t1h, t1l, w2h, w2l, b2,
                                       msg, nullptr, nullptr, nullptr, t2h, t2l);
    gemm_mma<2><<<ggrid, 256, GSMEM>>>(nullptr, t2h, t2l, w3h, w3l, b3,
                                       nullptr, e1, scale, out, nullptr, nullptr);
}